// round 11
// baseline (speedup 1.0000x reference)
#include <cuda_runtime.h>
#include <cuda_bf16.h>
#include <cstdint>

// ============================================================================
// Induction capsule routing, restructured (no e materialization):
//   c_i = (sum_s d_is x_is) @ W      (u_kernel; gemm NT)
//   b  += co * (x . (W c_raw))       (gemm TN; squash coeff folded into fused
//                                     reduce+b_update)
// Split-K (8) GEMM on mma.sync m16n8k16 bf16, 3-product bf16x2 split packed at
// staging into {hi}/{lo} smem words. Inner loop: LDS.32 + HMMA only.
// ============================================================================

static constexpr int C_CAPS = 64;
static constexpr int S_LEN  = 128;
static constexpr int H_DIM  = 2048;
static constexpr int KSPLIT = 8;
static constexpr int KLEN   = H_DIM / KSPLIT;   // 256 (16 chunks of 16)
static constexpr int NCHUNK = KLEN / 16;        // 16
static constexpr int BP     = 12;               // smem pitch (u32): conflict-free frags

// ---- scratch (device globals; allocation-free rule) ----
__device__ float g_b[C_CAPS * S_LEN];                       // logits
__device__ float g_u[C_CAPS * H_DIM];                       // weighted x sums
__device__ float g_part[KSPLIT][C_CAPS][H_DIM];             // split-K partials (4 MB)
__device__ float g_nrm2[C_CAPS][16];                        // per-block norm partials

__global__ void zero_b_kernel() {
    int i = blockIdx.x * blockDim.x + threadIdx.x;
    if (i < C_CAPS * S_LEN) g_b[i] = 0.0f;
}

// ============================================================================
// u_kernel: d = softmax(b[cap,:]); u[cap,h] = sum_s d[s] * x[cap,s,h]
// ============================================================================
__global__ void __launch_bounds__(256) u_kernel(const float* __restrict__ x) {
    const int cap = blockIdx.y;
    const int tid = threadIdx.x;
    const int h = blockIdx.x * 256 + tid;
    __shared__ float d[S_LEN];

    if (tid < S_LEN) d[tid] = g_b[cap * S_LEN + tid];
    __syncthreads();
    if (tid < 32) {
        float x0 = d[tid], x1 = d[tid + 32], x2 = d[tid + 64], x3 = d[tid + 96];
        float mx = fmaxf(fmaxf(x0, x1), fmaxf(x2, x3));
        #pragma unroll
        for (int o = 16; o > 0; o >>= 1) mx = fmaxf(mx, __shfl_xor_sync(0xffffffffu, mx, o));
        float e0 = __expf(x0 - mx), e1 = __expf(x1 - mx);
        float e2 = __expf(x2 - mx), e3 = __expf(x3 - mx);
        float s = (e0 + e1) + (e2 + e3);
        #pragma unroll
        for (int o = 16; o > 0; o >>= 1) s += __shfl_xor_sync(0xffffffffu, s, o);
        float inv = 1.0f / s;
        d[tid] = e0 * inv; d[tid + 32] = e1 * inv; d[tid + 64] = e2 * inv; d[tid + 96] = e3 * inv;
    }
    __syncthreads();

    const float* xp = x + (size_t)cap * S_LEN * H_DIM + h;
    float a0 = 0.f, a1 = 0.f, a2 = 0.f, a3 = 0.f;
    #pragma unroll 8
    for (int s = 0; s < S_LEN; s += 4) {
        a0 = fmaf(d[s + 0], xp[(size_t)(s + 0) * H_DIM], a0);
        a1 = fmaf(d[s + 1], xp[(size_t)(s + 1) * H_DIM], a1);
        a2 = fmaf(d[s + 2], xp[(size_t)(s + 2) * H_DIM], a2);
        a3 = fmaf(d[s + 3], xp[(size_t)(s + 3) * H_DIM], a3);
    }
    g_u[cap * H_DIM + h] = (a0 + a1) + (a2 + a3);
}

// ============================================================================
// bf16 split/pack helpers
// ============================================================================
static __device__ __forceinline__ void pack_split(float e, float o,
                                                  uint32_t& hi, uint32_t& lo) {
    __nv_bfloat162 h = __floats2bfloat162_rn(e, o);           // x=e(k even), y=o(k odd)
    float re = e - __bfloat162float(h.x);
    float ro = o - __bfloat162float(h.y);
    __nv_bfloat162 l = __floats2bfloat162_rn(re, ro);
    hi = *(uint32_t*)&h;
    lo = *(uint32_t*)&l;
}
static __device__ __forceinline__ void mma_bf16(float* c, const uint32_t* a,
                                                uint32_t b0, uint32_t b1) {
    asm("mma.sync.aligned.m16n8k16.row.col.f32.bf16.bf16.f32 "
        "{%0,%1,%2,%3}, {%4,%5,%6,%7}, {%8,%9}, {%0,%1,%2,%3};"
        : "+f"(c[0]), "+f"(c[1]), "+f"(c[2]), "+f"(c[3])
        : "r"(a[0]), "r"(a[1]), "r"(a[2]), "r"(a[3]), "r"(b0), "r"(b1));
}

// ============================================================================
// gemm_mma<BK_CONTIG>: g_part[kz][m][j] = sum_{k in chunk kz} A[m][k]*Bval(k,j)
//   BK_CONTIG=true  (TN): Bval(k,j) = B[(j0+j)*H + k]      (v = c @ W^T)
//   BK_CONTIG=false (NT): Bval(k,j) = B[k*H + (j0+j)]      (c = u @ W)
//   grid (64, 8) = 512 CTAs, block 128 (4 warps). CTA tile M=64 x N=32,
//   K=256 in 16 chunks of 16. Smem: packed bf16x2 hi/lo, pitch 12.
// ============================================================================
template <bool BK_CONTIG>
__global__ void __launch_bounds__(128) gemm_mma_kernel(const float* __restrict__ A,
                                                       const float* __restrict__ B) {
    __shared__ uint32_t Ahi[2][64][BP], Alo[2][64][BP];
    __shared__ uint32_t Bhi[2][32][BP], Blo[2][32][BP];

    const int tid = threadIdx.x;
    const int lane = tid & 31;
    const int w = tid >> 5;
    const int j0 = blockIdx.x * 32;
    const int kz = blockIdx.y;
    const int k0 = kz * KLEN;

    // ---- A staging slots: 2 float4 per thread (64 rows x 4 k-groups) ----
    const int am0 = tid >> 2,          ak0 = (tid & 3) * 4;
    const int am1 = (tid + 128) >> 2,  ak1 = ((tid + 128) & 3) * 4;
    const float* ap0 = A + (size_t)am0 * H_DIM + k0 + ak0;
    const float* ap1 = A + (size_t)am1 * H_DIM + k0 + ak1;

    // ---- B staging slots ----
    // TN: 1 float4 per thread (32 j-rows x 4 k-groups)
    const int jr = tid >> 2, kg = (tid & 3) * 4;
    const float* tp0 = B + (size_t)(j0 + jr) * H_DIM + k0 + kg;
    // NT: 1 slot: kp = tid>>4 (0..7 k-pairs), jq = tid&15 (2 j's each)
    const int kp = tid >> 4, jq = tid & 15;
    const float* np0 = B + (size_t)(k0 + 2 * kp) * H_DIM + j0 + 2 * jq;

    // prologue: chunk 0 global loads
    float4 ar0 = *(const float4*)ap0, ar1 = *(const float4*)ap1;
    float4 tb0;
    float2 nb0, nb1;
    if (BK_CONTIG) {
        tb0 = *(const float4*)tp0;
    } else {
        nb0 = *(const float2*)np0;
        nb1 = *(const float2*)(np0 + H_DIM);
    }

    const int g = lane >> 2, t = lane & 3;
    const int mrow = w * 16 + g;

    float acc[4][4] = {};

    for (int kc = 0; kc < NCHUNK; kc++) {
        const int cur = kc & 1;
        // ---- stage A (split+pack k-pairs) ----
        {
            uint32_t h, l;
            pack_split(ar0.x, ar0.y, h, l);
            Ahi[cur][am0][ak0 / 2] = h;     Alo[cur][am0][ak0 / 2] = l;
            pack_split(ar0.z, ar0.w, h, l);
            Ahi[cur][am0][ak0 / 2 + 1] = h; Alo[cur][am0][ak0 / 2 + 1] = l;
            pack_split(ar1.x, ar1.y, h, l);
            Ahi[cur][am1][ak1 / 2] = h;     Alo[cur][am1][ak1 / 2] = l;
            pack_split(ar1.z, ar1.w, h, l);
            Ahi[cur][am1][ak1 / 2 + 1] = h; Alo[cur][am1][ak1 / 2 + 1] = l;
        }
        // ---- stage B ----
        if (BK_CONTIG) {
            uint32_t h, l;
            pack_split(tb0.x, tb0.y, h, l);
            Bhi[cur][jr][kg / 2] = h;     Blo[cur][jr][kg / 2] = l;
            pack_split(tb0.z, tb0.w, h, l);
            Bhi[cur][jr][kg / 2 + 1] = h; Blo[cur][jr][kg / 2 + 1] = l;
        } else {
            uint32_t h, l;
            pack_split(nb0.x, nb1.x, h, l);         // j = 2*jq
            Bhi[cur][2 * jq][kp] = h;     Blo[cur][2 * jq][kp] = l;
            pack_split(nb0.y, nb1.y, h, l);         // j = 2*jq+1
            Bhi[cur][2 * jq + 1][kp] = h; Blo[cur][2 * jq + 1][kp] = l;
        }
        __syncthreads();

        // ---- prefetch next chunk ----
        if (kc + 1 < NCHUNK) {
            const int ko = (kc + 1) * 16;
            ar0 = *(const float4*)(ap0 + ko);
            ar1 = *(const float4*)(ap1 + ko);
            if (BK_CONTIG) {
                tb0 = *(const float4*)(tp0 + ko);
            } else {
                const size_t ro = (size_t)ko * H_DIM;
                nb0 = *(const float2*)(np0 + ro);
                nb1 = *(const float2*)(np0 + ro + H_DIM);
            }
        }

        // ---- fragments + mma: whole k16, no split ops ----
        uint32_t ah[4], al[4];
        ah[0] = Ahi[cur][mrow    ][t];     al[0] = Alo[cur][mrow    ][t];
        ah[1] = Ahi[cur][mrow + 8][t];     al[1] = Alo[cur][mrow + 8][t];
        ah[2] = Ahi[cur][mrow    ][t + 4]; al[2] = Alo[cur][mrow    ][t + 4];
        ah[3] = Ahi[cur][mrow + 8][t + 4]; al[3] = Alo[cur][mrow + 8][t + 4];
        #pragma unroll
        for (int nt = 0; nt < 4; nt++) {
            const int bn = nt * 8 + g;
            uint32_t bh0 = Bhi[cur][bn][t], bh1 = Bhi[cur][bn][t + 4];
            uint32_t bl0 = Blo[cur][bn][t], bl1 = Blo[cur][bn][t + 4];
            mma_bf16(acc[nt], ah, bh0, bh1);   // hi*hi
            mma_bf16(acc[nt], ah, bl0, bl1);   // hi*lo
            mma_bf16(acc[nt], al, bh0, bh1);   // lo*hi
        }
        // single barrier per chunk: iteration kc+2's stores to this buffer sit
        // behind barrier kc+1, which this warp only reaches after this compute.
    }

    // epilogue: c0=(g,2t) c1=(g,2t+1) c2=(g+8,2t) c3=(g+8,2t+1) per n-tile
    #pragma unroll
    for (int nt = 0; nt < 4; nt++) {
        const int col = j0 + nt * 8 + 2 * t;
        *(float2*)&g_part[kz][mrow    ][col] = make_float2(acc[nt][0], acc[nt][1]);
        *(float2*)&g_part[kz][mrow + 8][col] = make_float2(acc[nt][2], acc[nt][3]);
    }
}

// ============================================================================
// z-split reduce (8 planes): lane = (zq<<3)|jj; each lane sums 2 planes, then
// 2 shfl rounds (fixed order, deterministic).
// ============================================================================
static __device__ __forceinline__ float4 zsplit_sum(int cap, int j, int zq) {
    float4 a = make_float4(0.f, 0.f, 0.f, 0.f);
    #pragma unroll
    for (int i = 0; i < 2; i++) {
        float4 p = *(const float4*)&g_part[zq * 2 + i][cap][j];
        a.x += p.x; a.y += p.y; a.z += p.z; a.w += p.w;
    }
    #pragma unroll
    for (int o = 8; o <= 16; o <<= 1) {
        a.x += __shfl_xor_sync(0xffffffffu, a.x, o);
        a.y += __shfl_xor_sync(0xffffffffu, a.y, o);
        a.z += __shfl_xor_sync(0xffffffffu, a.z, o);
        a.w += __shfl_xor_sync(0xffffffffu, a.w, o);
    }
    return a;
}

// ============================================================================
// reduce_c_norm: out[cap][:] = sum_z g_part[z][cap][:] (RAW c); g_nrm2 partials.
//   grid (16, 64) = 1024 CTAs, block 128.
// ============================================================================
__global__ void __launch_bounds__(128) reduce_c_norm_kernel(float* __restrict__ out) {
    const int cap = blockIdx.y;
    const int jb = blockIdx.x;
    const int tid = threadIdx.x;
    const int w = tid >> 5, lane = tid & 31;
    const int jj = lane & 7, zq = lane >> 3;
    const int j = (jb * 32 + w * 8 + jj) * 4;

    float4 a = zsplit_sum(cap, j, zq);
    if (zq == 0) *(float4*)(out + cap * H_DIM + j) = a;

    float sq = a.x * a.x + a.y * a.y + a.z * a.z + a.w * a.w;
    #pragma unroll
    for (int o = 1; o <= 4; o <<= 1) sq += __shfl_xor_sync(0xffffffffu, sq, o);
    __shared__ float ws[4];
    if (lane == 0) ws[w] = sq;
    __syncthreads();
    if (tid == 0) g_nrm2[cap][jb] = (ws[0] + ws[1]) + (ws[2] + ws[3]);
}

// ============================================================================
// squash_scale (final iteration only): coeff from 16 norm partials; scale out.
// ============================================================================
__global__ void __launch_bounds__(256) squash_scale_kernel(float* __restrict__ out) {
    const int cap = blockIdx.x;
    const int tid = threadIdx.x;
    __shared__ float coeff_s;
    if (tid == 0) {
        float s = 0.f;
        #pragma unroll
        for (int k = 0; k < 16; k++) s += g_nrm2[cap][k];
        coeff_s = s / (1.0f + s) / sqrtf(s + 1e-9f);
    }
    __syncthreads();
    const float co = coeff_s;
    float* row = out + cap * H_DIM;
    #pragma unroll
    for (int r = 0; r < 2; r++) {
        int j = (tid + 256 * r) * 4;
        float4 v = *(float4*)(row + j);
        *(float4*)(row + j) = make_float4(v.x * co, v.y * co, v.z * co, v.w * co);
    }
}

// ============================================================================
// b_update (fused): coeff from g_nrm2; v = co * sum_z part[z][cap][:] -> smem;
// b[cap,s] += x[cap,s,:] . v.   grid (4, 64), block 1024; warp per s.
// ============================================================================
__global__ void __launch_bounds__(1024) b_update_kernel(const float* __restrict__ x) {
    const int cap = blockIdx.y;
    const int sb = blockIdx.x;
    const int tid = threadIdx.x;
    __shared__ float vs[H_DIM];
    __shared__ float coeff_s;

    if (tid == 0) {
        float s = 0.f;
        #pragma unroll
        for (int k = 0; k < 16; k++) s += g_nrm2[cap][k];
        coeff_s = s / (1.0f + s) / sqrtf(s + 1e-9f);
    }
    __syncthreads();
    const float co = coeff_s;

    if (tid < 512) {
        const int j = tid * 4;
        float4 a = make_float4(0.f, 0.f, 0.f, 0.f);
        #pragma unroll
        for (int z = 0; z < KSPLIT; z++) {
            float4 p = *(const float4*)&g_part[z][cap][j];
            a.x += p.x; a.y += p.y; a.z += p.z; a.w += p.w;
        }
        *(float4*)(vs + j) = make_float4(a.x * co, a.y * co, a.z * co, a.w * co);
    }
    __syncthreads();

    const int warp = tid >> 5, lane = tid & 31;
    const int s = sb * 32 + warp;
    const float4* xp = (const float4*)(x + ((size_t)cap * S_LEN + s) * H_DIM);
    const float4* vp = (const float4*)vs;
    float acc = 0.f;
    #pragma unroll 4
    for (int j = lane; j < H_DIM / 4; j += 32) {
        float4 ev = xp[j], cv = vp[j];
        acc = fmaf(ev.x, cv.x, acc);
        acc = fmaf(ev.y, cv.y, acc);
        acc = fmaf(ev.z, cv.z, acc);
        acc = fmaf(ev.w, cv.w, acc);
    }
    #pragma unroll
    for (int o = 16; o > 0; o >>= 1) acc += __shfl_xor_sync(0xffffffffu, acc, o);
    if (lane == 0) g_b[cap * S_LEN + s] += acc;
}

// ============================================================================
// kernel_launch
// ============================================================================
extern "C" void kernel_launch(void* const* d_in, const int* in_sizes, int n_in,
                              void* d_out, int out_size) {
    const float* x = (const float*)d_in[0];   // [64,128,2048] fp32
    const float* W = (const float*)d_in[1];   // [2048,2048] fp32
    float* out = (float*)d_out;               // [64,2048] fp32 — holds c

    float* u_ptr;
    cudaGetSymbolAddress((void**)&u_ptr, g_u);

    const dim3 gemm_grid(H_DIM / 32, KSPLIT);

    zero_b_kernel<<<8, 1024>>>();

    for (int it = 0; it < 3; ++it) {
        u_kernel<<<dim3(H_DIM / 256, C_CAPS), 256>>>(x);
        gemm_mma_kernel<false><<<gemm_grid, 128>>>(u_ptr, W);        // c_raw = u @ W
        reduce_c_norm_kernel<<<dim3(16, C_CAPS), 128>>>(out);        // out = c_raw
        if (it < 2) {
            gemm_mma_kernel<true><<<gemm_grid, 128>>>(out, W);       // part = c_raw @ W^T
            b_update_kernel<<<dim3(4, C_CAPS), 1024>>>(x);           // fused v+squash+dot
        } else {
            squash_scale_kernel<<<C_CAPS, 256>>>(out);               // final squash
        }
    }
}

// round 12
// speedup vs baseline: 1.0302x; 1.0302x over previous
#include <cuda_runtime.h>
#include <cuda_bf16.h>
#include <cstdint>

// ============================================================================
// Induction capsule routing, restructured (no e materialization):
//   c_i = (sum_s d_is x_is) @ W      (u_kernel; gemm NT)
//   b  += co * (x . (W c_raw))       (gemm TN; squash folded into fused b_update)
// Split-K(16) GEMM on mma.sync m16n8k16 bf16, 3-product bf16x2 split packed at
// staging into {hi}/{lo} smem. Block 256 (8 warps) for staging/latency overlap.
// ============================================================================

static constexpr int C_CAPS = 64;
static constexpr int S_LEN  = 128;
static constexpr int H_DIM  = 2048;
static constexpr int KSPLIT = 16;
static constexpr int KLEN   = H_DIM / KSPLIT;   // 128 (8 chunks of 16)
static constexpr int NCHUNK = KLEN / 16;        // 8
static constexpr int BP     = 12;               // smem pitch (u32): conflict-free frags

// ---- scratch (device globals; allocation-free rule) ----
__device__ float g_b[C_CAPS * S_LEN];                       // logits
__device__ float g_u[C_CAPS * H_DIM];                       // weighted x sums
__device__ float g_part[KSPLIT][C_CAPS][H_DIM];             // split-K partials (8 MB)
__device__ float g_nrm2[C_CAPS][16];                        // per-block norm partials

__global__ void zero_b_kernel() {
    int i = blockIdx.x * blockDim.x + threadIdx.x;
    if (i < C_CAPS * S_LEN) g_b[i] = 0.0f;
}

// ============================================================================
// u_kernel: d = softmax(b[cap,:]); u[cap,h] = sum_s d[s] * x[cap,s,h]
// ============================================================================
__global__ void __launch_bounds__(256) u_kernel(const float* __restrict__ x) {
    const int cap = blockIdx.y;
    const int tid = threadIdx.x;
    const int h = blockIdx.x * 256 + tid;
    __shared__ float d[S_LEN];

    if (tid < S_LEN) d[tid] = g_b[cap * S_LEN + tid];
    __syncthreads();
    if (tid < 32) {
        float x0 = d[tid], x1 = d[tid + 32], x2 = d[tid + 64], x3 = d[tid + 96];
        float mx = fmaxf(fmaxf(x0, x1), fmaxf(x2, x3));
        #pragma unroll
        for (int o = 16; o > 0; o >>= 1) mx = fmaxf(mx, __shfl_xor_sync(0xffffffffu, mx, o));
        float e0 = __expf(x0 - mx), e1 = __expf(x1 - mx);
        float e2 = __expf(x2 - mx), e3 = __expf(x3 - mx);
        float s = (e0 + e1) + (e2 + e3);
        #pragma unroll
        for (int o = 16; o > 0; o >>= 1) s += __shfl_xor_sync(0xffffffffu, s, o);
        float inv = 1.0f / s;
        d[tid] = e0 * inv; d[tid + 32] = e1 * inv; d[tid + 64] = e2 * inv; d[tid + 96] = e3 * inv;
    }
    __syncthreads();

    const float* xp = x + (size_t)cap * S_LEN * H_DIM + h;
    float a0 = 0.f, a1 = 0.f, a2 = 0.f, a3 = 0.f;
    #pragma unroll 8
    for (int s = 0; s < S_LEN; s += 4) {
        a0 = fmaf(d[s + 0], xp[(size_t)(s + 0) * H_DIM], a0);
        a1 = fmaf(d[s + 1], xp[(size_t)(s + 1) * H_DIM], a1);
        a2 = fmaf(d[s + 2], xp[(size_t)(s + 2) * H_DIM], a2);
        a3 = fmaf(d[s + 3], xp[(size_t)(s + 3) * H_DIM], a3);
    }
    g_u[cap * H_DIM + h] = (a0 + a1) + (a2 + a3);
}

// ============================================================================
// bf16 split/pack helpers
// ============================================================================
static __device__ __forceinline__ void pack_split(float e, float o,
                                                  uint32_t& hi, uint32_t& lo) {
    __nv_bfloat162 h = __floats2bfloat162_rn(e, o);           // x=e(k even), y=o(k odd)
    float re = e - __bfloat162float(h.x);
    float ro = o - __bfloat162float(h.y);
    __nv_bfloat162 l = __floats2bfloat162_rn(re, ro);
    hi = *(uint32_t*)&h;
    lo = *(uint32_t*)&l;
}
static __device__ __forceinline__ void mma_bf16(float* c, const uint32_t* a,
                                                uint32_t b0, uint32_t b1) {
    asm("mma.sync.aligned.m16n8k16.row.col.f32.bf16.bf16.f32 "
        "{%0,%1,%2,%3}, {%4,%5,%6,%7}, {%8,%9}, {%0,%1,%2,%3};"
        : "+f"(c[0]), "+f"(c[1]), "+f"(c[2]), "+f"(c[3])
        : "r"(a[0]), "r"(a[1]), "r"(a[2]), "r"(a[3]), "r"(b0), "r"(b1));
}

// ============================================================================
// gemm_mma<BK_CONTIG>: g_part[kz][m][j] = sum_{k in chunk kz} A[m][k]*Bval(k,j)
//   BK_CONTIG=true  (TN): Bval(k,j) = B[(j0+j)*H + k]      (v = c @ W^T)
//   BK_CONTIG=false (NT): Bval(k,j) = B[k*H + (j0+j)]      (c = u @ W)
//   grid (32, 16) = 512 CTAs, block 256 (8 warps). CTA tile M=64 x N=64,
//   K=128 in 8 chunks of 16. Warp w: m rows [16(w&3),+16), n half (w>>2)*32.
//   Smem: packed bf16x2 hi/lo, pitch 12. Staging: 1 float4/thread/operand.
// ============================================================================
template <bool BK_CONTIG>
__global__ void __launch_bounds__(256) gemm_mma_kernel(const float* __restrict__ A,
                                                       const float* __restrict__ B) {
    __shared__ uint32_t Ahi[2][64][BP], Alo[2][64][BP];
    __shared__ uint32_t Bhi[2][64][BP], Blo[2][64][BP];

    const int tid = threadIdx.x;
    const int lane = tid & 31;
    const int w = tid >> 5;
    const int j0 = blockIdx.x * 64;
    const int kz = blockIdx.y;
    const int k0 = kz * KLEN;

    // ---- A staging: 1 float4 per thread (64 rows x 4 k-groups = 256 slots) ----
    const int am = tid >> 2, ak = (tid & 3) * 4;
    const float* ap = A + (size_t)am * H_DIM + k0 + ak;

    // ---- B staging slots ----
    // TN: 1 float4 per thread (64 j-rows x 4 k-groups)
    const float* tp = B + (size_t)(j0 + am) * H_DIM + k0 + ak;
    // NT: 1 slot: kp = tid>>5 (0..7 k-pairs), jq = tid&31 (2 j's each)
    const int kp = tid >> 5, jq = tid & 31;
    const float* np = B + (size_t)(k0 + 2 * kp) * H_DIM + j0 + 2 * jq;

    // prologue: chunk 0 global loads
    float4 ar = *(const float4*)ap;
    float4 tb;
    float2 nb0, nb1;
    if (BK_CONTIG) {
        tb = *(const float4*)tp;
    } else {
        nb0 = *(const float2*)np;
        nb1 = *(const float2*)(np + H_DIM);
    }

    const int g = lane >> 2, t = lane & 3;
    const int mrow = (w & 3) * 16 + g;
    const int nbase = (w >> 2) * 32;

    float acc[4][4] = {};

    for (int kc = 0; kc < NCHUNK; kc++) {
        const int cur = kc & 1;
        // ---- stage A (split+pack k-pairs) ----
        {
            uint32_t h, l;
            pack_split(ar.x, ar.y, h, l);
            Ahi[cur][am][ak / 2] = h;     Alo[cur][am][ak / 2] = l;
            pack_split(ar.z, ar.w, h, l);
            Ahi[cur][am][ak / 2 + 1] = h; Alo[cur][am][ak / 2 + 1] = l;
        }
        // ---- stage B ----
        if (BK_CONTIG) {
            uint32_t h, l;
            pack_split(tb.x, tb.y, h, l);
            Bhi[cur][am][ak / 2] = h;     Blo[cur][am][ak / 2] = l;
            pack_split(tb.z, tb.w, h, l);
            Bhi[cur][am][ak / 2 + 1] = h; Blo[cur][am][ak / 2 + 1] = l;
        } else {
            uint32_t h, l;
            pack_split(nb0.x, nb1.x, h, l);         // j = 2*jq
            Bhi[cur][2 * jq][kp] = h;     Blo[cur][2 * jq][kp] = l;
            pack_split(nb0.y, nb1.y, h, l);         // j = 2*jq+1
            Bhi[cur][2 * jq + 1][kp] = h; Blo[cur][2 * jq + 1][kp] = l;
        }
        __syncthreads();

        // ---- prefetch next chunk ----
        if (kc + 1 < NCHUNK) {
            const int ko = (kc + 1) * 16;
            ar = *(const float4*)(ap + ko);
            if (BK_CONTIG) {
                tb = *(const float4*)(tp + ko);
            } else {
                const size_t ro = (size_t)ko * H_DIM;
                nb0 = *(const float2*)(np + ro);
                nb1 = *(const float2*)(np + ro + H_DIM);
            }
        }

        // ---- fragments + mma: whole k16, no split ops ----
        uint32_t ah[4], al[4];
        ah[0] = Ahi[cur][mrow    ][t];     al[0] = Alo[cur][mrow    ][t];
        ah[1] = Ahi[cur][mrow + 8][t];     al[1] = Alo[cur][mrow + 8][t];
        ah[2] = Ahi[cur][mrow    ][t + 4]; al[2] = Alo[cur][mrow    ][t + 4];
        ah[3] = Ahi[cur][mrow + 8][t + 4]; al[3] = Alo[cur][mrow + 8][t + 4];
        #pragma unroll
        for (int nt = 0; nt < 4; nt++) {
            const int bn = nbase + nt * 8 + g;
            uint32_t bh0 = Bhi[cur][bn][t], bh1 = Bhi[cur][bn][t + 4];
            uint32_t bl0 = Blo[cur][bn][t], bl1 = Blo[cur][bn][t + 4];
            mma_bf16(acc[nt], ah, bh0, bh1);   // hi*hi
            mma_bf16(acc[nt], ah, bl0, bl1);   // hi*lo
            mma_bf16(acc[nt], al, bh0, bh1);   // lo*hi
        }
        // single barrier per chunk: iteration kc+2's stores to this buffer sit
        // behind barrier kc+1, which this warp only reaches after this compute.
    }

    // epilogue: c0=(g,2t) c1=(g,2t+1) c2=(g+8,2t) c3=(g+8,2t+1) per n-tile
    #pragma unroll
    for (int nt = 0; nt < 4; nt++) {
        const int col = j0 + nbase + nt * 8 + 2 * t;
        *(float2*)&g_part[kz][mrow    ][col] = make_float2(acc[nt][0], acc[nt][1]);
        *(float2*)&g_part[kz][mrow + 8][col] = make_float2(acc[nt][2], acc[nt][3]);
    }
}

// ============================================================================
// z-split reduce (16 planes): lane = (zq<<3)|jj; each lane sums 4 planes, then
// 2 shfl rounds (fixed order, deterministic).
// ============================================================================
static __device__ __forceinline__ float4 zsplit_sum(int cap, int j, int zq) {
    float4 a = make_float4(0.f, 0.f, 0.f, 0.f);
    #pragma unroll
    for (int i = 0; i < 4; i++) {
        float4 p = *(const float4*)&g_part[zq * 4 + i][cap][j];
        a.x += p.x; a.y += p.y; a.z += p.z; a.w += p.w;
    }
    #pragma unroll
    for (int o = 8; o <= 16; o <<= 1) {
        a.x += __shfl_xor_sync(0xffffffffu, a.x, o);
        a.y += __shfl_xor_sync(0xffffffffu, a.y, o);
        a.z += __shfl_xor_sync(0xffffffffu, a.z, o);
        a.w += __shfl_xor_sync(0xffffffffu, a.w, o);
    }
    return a;
}

// ============================================================================
// reduce_c_norm: out[cap][:] = sum_z g_part[z][cap][:] (RAW c); g_nrm2 partials.
//   grid (16, 64) = 1024 CTAs, block 128.
// ============================================================================
__global__ void __launch_bounds__(128) reduce_c_norm_kernel(float* __restrict__ out) {
    const int cap = blockIdx.y;
    const int jb = blockIdx.x;
    const int tid = threadIdx.x;
    const int w = tid >> 5, lane = tid & 31;
    const int jj = lane & 7, zq = lane >> 3;
    const int j = (jb * 32 + w * 8 + jj) * 4;

    float4 a = zsplit_sum(cap, j, zq);
    if (zq == 0) *(float4*)(out + cap * H_DIM + j) = a;

    float sq = a.x * a.x + a.y * a.y + a.z * a.z + a.w * a.w;
    #pragma unroll
    for (int o = 1; o <= 4; o <<= 1) sq += __shfl_xor_sync(0xffffffffu, sq, o);
    __shared__ float ws[4];
    if (lane == 0) ws[w] = sq;
    __syncthreads();
    if (tid == 0) g_nrm2[cap][jb] = (ws[0] + ws[1]) + (ws[2] + ws[3]);
}

// ============================================================================
// squash_scale (final iteration only): coeff from 16 norm partials; scale out.
// ============================================================================
__global__ void __launch_bounds__(256) squash_scale_kernel(float* __restrict__ out) {
    const int cap = blockIdx.x;
    const int tid = threadIdx.x;
    __shared__ float coeff_s;
    if (tid == 0) {
        float s = 0.f;
        #pragma unroll
        for (int k = 0; k < 16; k++) s += g_nrm2[cap][k];
        coeff_s = s / (1.0f + s) / sqrtf(s + 1e-9f);
    }
    __syncthreads();
    const float co = coeff_s;
    float* row = out + cap * H_DIM;
    #pragma unroll
    for (int r = 0; r < 2; r++) {
        int j = (tid + 256 * r) * 4;
        float4 v = *(float4*)(row + j);
        *(float4*)(row + j) = make_float4(v.x * co, v.y * co, v.z * co, v.w * co);
    }
}

// ============================================================================
// b_update (fused): coeff from g_nrm2; v = co * sum_z part[z][cap][:] -> smem;
// b[cap,s] += x[cap,s,:] . v.   grid (4, 64), block 1024; warp per s.
// ============================================================================
__global__ void __launch_bounds__(1024) b_update_kernel(const float* __restrict__ x) {
    const int cap = blockIdx.y;
    const int sb = blockIdx.x;
    const int tid = threadIdx.x;
    __shared__ float vs[H_DIM];
    __shared__ float coeff_s;

    if (tid == 0) {
        float s = 0.f;
        #pragma unroll
        for (int k = 0; k < 16; k++) s += g_nrm2[cap][k];
        coeff_s = s / (1.0f + s) / sqrtf(s + 1e-9f);
    }
    __syncthreads();
    const float co = coeff_s;

    if (tid < 512) {
        const int j = tid * 4;
        float4 a = make_float4(0.f, 0.f, 0.f, 0.f);
        #pragma unroll
        for (int z = 0; z < KSPLIT; z++) {
            float4 p = *(const float4*)&g_part[z][cap][j];
            a.x += p.x; a.y += p.y; a.z += p.z; a.w += p.w;
        }
        *(float4*)(vs + j) = make_float4(a.x * co, a.y * co, a.z * co, a.w * co);
    }
    __syncthreads();

    const int warp = tid >> 5, lane = tid & 31;
    const int s = sb * 32 + warp;
    const float4* xp = (const float4*)(x + ((size_t)cap * S_LEN + s) * H_DIM);
    const float4* vp = (const float4*)vs;
    float acc = 0.f;
    #pragma unroll 4
    for (int j = lane; j < H_DIM / 4; j += 32) {
        float4 ev = xp[j], cv = vp[j];
        acc = fmaf(ev.x, cv.x, acc);
        acc = fmaf(ev.y, cv.y, acc);
        acc = fmaf(ev.z, cv.z, acc);
        acc = fmaf(ev.w, cv.w, acc);
    }
    #pragma unroll
    for (int o = 16; o > 0; o >>= 1) acc += __shfl_xor_sync(0xffffffffu, acc, o);
    if (lane == 0) g_b[cap * S_LEN + s] += acc;
}

// ============================================================================
// kernel_launch
// ============================================================================
extern "C" void kernel_launch(void* const* d_in, const int* in_sizes, int n_in,
                              void* d_out, int out_size) {
    const float* x = (const float*)d_in[0];   // [64,128,2048] fp32
    const float* W = (const float*)d_in[1];   // [2048,2048] fp32
    float* out = (float*)d_out;               // [64,2048] fp32 — holds c

    float* u_ptr;
    cudaGetSymbolAddress((void**)&u_ptr, g_u);

    const dim3 gemm_grid(H_DIM / 64, KSPLIT);

    zero_b_kernel<<<8, 1024>>>();

    for (int it = 0; it < 3; ++it) {
        u_kernel<<<dim3(H_DIM / 256, C_CAPS), 256>>>(x);
        gemm_mma_kernel<false><<<gemm_grid, 256>>>(u_ptr, W);        // c_raw = u @ W
        reduce_c_norm_kernel<<<dim3(16, C_CAPS), 128>>>(out);        // out = c_raw
        if (it < 2) {
            gemm_mma_kernel<true><<<gemm_grid, 256>>>(out, W);       // part = c_raw @ W^T
            b_update_kernel<<<dim3(4, C_CAPS), 1024>>>(x);           // fused v+squash+dot
        } else {
            squash_scale_kernel<<<C_CAPS, 256>>>(out);               // final squash
        }
    }
}

// round 13
// speedup vs baseline: 1.0942x; 1.0621x over previous
#include <cuda_runtime.h>
#include <cuda_bf16.h>
#include <cstdint>

// ============================================================================
// Induction capsule routing, restructured (no e materialization):
//   c_i = (sum_s d_is x_is) @ W      (u_kernel; gemm NT)
//   b  += co * (x . (W c_raw))       (gemm TN; squash folded into fused b_update)
// Split-K(16) GEMM on mma.sync m16n8k16 bf16, 3-product bf16x2 split packed at
// staging. Block 128, k32 chunks (half the barriers of k16), double-buffered.
// Iteration 0 specialized: uniform softmax, b stored (no zero kernel).
// ============================================================================

static constexpr int C_CAPS = 64;
static constexpr int S_LEN  = 128;
static constexpr int H_DIM  = 2048;
static constexpr int KSPLIT = 16;
static constexpr int KLEN   = H_DIM / KSPLIT;   // 128 -> 4 chunks of 32
static constexpr int NCHUNK = KLEN / 32;        // 4
static constexpr int BP     = 20;               // smem pitch (u32): 16 k-pairs + pad

// ---- scratch (device globals; allocation-free rule) ----
__device__ float g_b[C_CAPS * S_LEN];                       // logits
__device__ float g_u[C_CAPS * H_DIM];                       // weighted x sums
__device__ float g_part[KSPLIT][C_CAPS][H_DIM];             // split-K partials (8 MB)
__device__ float g_nrm2[C_CAPS][16];                        // per-block norm partials

// ============================================================================
// u_kernel<FIRST>: FIRST -> d uniform (b==0); else d = softmax(b[cap,:]).
// u[cap,h] = sum_s d[s] * x[cap,s,h].  grid (8, 64), block 256.
// ============================================================================
template <bool FIRST>
__global__ void __launch_bounds__(256) u_kernel(const float* __restrict__ x) {
    const int cap = blockIdx.y;
    const int tid = threadIdx.x;
    const int h = blockIdx.x * 256 + tid;
    __shared__ float d[S_LEN];

    if (!FIRST) {
        if (tid < S_LEN) d[tid] = g_b[cap * S_LEN + tid];
        __syncthreads();
        if (tid < 32) {
            float x0 = d[tid], x1 = d[tid + 32], x2 = d[tid + 64], x3 = d[tid + 96];
            float mx = fmaxf(fmaxf(x0, x1), fmaxf(x2, x3));
            #pragma unroll
            for (int o = 16; o > 0; o >>= 1) mx = fmaxf(mx, __shfl_xor_sync(0xffffffffu, mx, o));
            float e0 = __expf(x0 - mx), e1 = __expf(x1 - mx);
            float e2 = __expf(x2 - mx), e3 = __expf(x3 - mx);
            float s = (e0 + e1) + (e2 + e3);
            #pragma unroll
            for (int o = 16; o > 0; o >>= 1) s += __shfl_xor_sync(0xffffffffu, s, o);
            float inv = 1.0f / s;
            d[tid] = e0 * inv; d[tid + 32] = e1 * inv;
            d[tid + 64] = e2 * inv; d[tid + 96] = e3 * inv;
        }
        __syncthreads();
    }

    const float* xp = x + (size_t)cap * S_LEN * H_DIM + h;
    float a0 = 0.f, a1 = 0.f, a2 = 0.f, a3 = 0.f;
    if (FIRST) {
        #pragma unroll 8
        for (int s = 0; s < S_LEN; s += 4) {
            a0 += xp[(size_t)(s + 0) * H_DIM];
            a1 += xp[(size_t)(s + 1) * H_DIM];
            a2 += xp[(size_t)(s + 2) * H_DIM];
            a3 += xp[(size_t)(s + 3) * H_DIM];
        }
        g_u[cap * H_DIM + h] = ((a0 + a1) + (a2 + a3)) * (1.0f / S_LEN);
    } else {
        #pragma unroll 8
        for (int s = 0; s < S_LEN; s += 4) {
            a0 = fmaf(d[s + 0], xp[(size_t)(s + 0) * H_DIM], a0);
            a1 = fmaf(d[s + 1], xp[(size_t)(s + 1) * H_DIM], a1);
            a2 = fmaf(d[s + 2], xp[(size_t)(s + 2) * H_DIM], a2);
            a3 = fmaf(d[s + 3], xp[(size_t)(s + 3) * H_DIM], a3);
        }
        g_u[cap * H_DIM + h] = (a0 + a1) + (a2 + a3);
    }
}

// ============================================================================
// bf16 split/pack helpers
// ============================================================================
static __device__ __forceinline__ void pack_split(float e, float o,
                                                  uint32_t& hi, uint32_t& lo) {
    __nv_bfloat162 h = __floats2bfloat162_rn(e, o);           // x=e(k even), y=o(k odd)
    float re = e - __bfloat162float(h.x);
    float ro = o - __bfloat162float(h.y);
    __nv_bfloat162 l = __floats2bfloat162_rn(re, ro);
    hi = *(uint32_t*)&h;
    lo = *(uint32_t*)&l;
}
static __device__ __forceinline__ void mma_bf16(float* c, const uint32_t* a,
                                                uint32_t b0, uint32_t b1) {
    asm("mma.sync.aligned.m16n8k16.row.col.f32.bf16.bf16.f32 "
        "{%0,%1,%2,%3}, {%4,%5,%6,%7}, {%8,%9}, {%0,%1,%2,%3};"
        : "+f"(c[0]), "+f"(c[1]), "+f"(c[2]), "+f"(c[3])
        : "r"(a[0]), "r"(a[1]), "r"(a[2]), "r"(a[3]), "r"(b0), "r"(b1));
}

// ============================================================================
// gemm_mma<BK_CONTIG>: g_part[kz][m][j] = sum_{k in chunk kz} A[m][k]*Bval(k,j)
//   BK_CONTIG=true  (TN): Bval(k,j) = B[(j0+j)*H + k]      (v = c @ W^T)
//   BK_CONTIG=false (NT): Bval(k,j) = B[k*H + (j0+j)]      (c = u @ W)
//   grid (32, 16) = 512 CTAs, block 128 (4 warps). CTA tile M=64 x N=64,
//   K=128 in 4 chunks of 32 (double-buffered, 1 barrier per chunk).
//   Smem: packed bf16x2 hi/lo, pitch 20 (conflict-free fragment LDS).
// ============================================================================
template <bool BK_CONTIG>
__global__ void __launch_bounds__(128) gemm_mma_kernel(const float* __restrict__ A,
                                                       const float* __restrict__ B) {
    __shared__ uint32_t Ahi[2][64][BP], Alo[2][64][BP];
    __shared__ uint32_t Bhi[2][64][BP], Blo[2][64][BP];

    const int tid = threadIdx.x;
    const int lane = tid & 31;
    const int w = tid >> 5;
    const int j0 = blockIdx.x * 64;
    const int kz = blockIdx.y;
    const int k0 = kz * KLEN;

    // ---- staging slots: 4 per thread (64 rows x 8 f4-kgroups = 512 slots) ----
    int am[4], ak[4];
    const float* ap[4];
    const float* tp[4];
    int kp[4], jq[4];
    const float* np[4];
    #pragma unroll
    for (int i = 0; i < 4; i++) {
        const int s = tid + 128 * i;
        am[i] = s >> 3; ak[i] = (s & 7) * 4;
        ap[i] = A + (size_t)am[i] * H_DIM + k0 + ak[i];
        tp[i] = B + (size_t)(j0 + am[i]) * H_DIM + k0 + ak[i];
        kp[i] = s >> 5; jq[i] = s & 31;            // 16 k-pairs x 32 j-pairs
        np[i] = B + (size_t)(k0 + 2 * kp[i]) * H_DIM + j0 + 2 * jq[i];
    }

    // prologue: chunk 0 global loads
    float4 ar[4], tb[4];
    float2 nb0[4], nb1[4];
    #pragma unroll
    for (int i = 0; i < 4; i++) {
        ar[i] = *(const float4*)ap[i];
        if (BK_CONTIG) {
            tb[i] = *(const float4*)tp[i];
        } else {
            nb0[i] = *(const float2*)np[i];
            nb1[i] = *(const float2*)(np[i] + H_DIM);
        }
    }

    const int g = lane >> 2, t = lane & 3;
    const int mrow = w * 16 + g;

    float acc[8][4] = {};

    for (int kc = 0; kc < NCHUNK; kc++) {
        const int cur = kc & 1;
        // ---- stage (split+pack k-pairs) ----
        #pragma unroll
        for (int i = 0; i < 4; i++) {
            uint32_t h, l;
            const int kq = ak[i] / 2;
            pack_split(ar[i].x, ar[i].y, h, l);
            Ahi[cur][am[i]][kq] = h;     Alo[cur][am[i]][kq] = l;
            pack_split(ar[i].z, ar[i].w, h, l);
            Ahi[cur][am[i]][kq + 1] = h; Alo[cur][am[i]][kq + 1] = l;
            if (BK_CONTIG) {
                pack_split(tb[i].x, tb[i].y, h, l);
                Bhi[cur][am[i]][kq] = h;     Blo[cur][am[i]][kq] = l;
                pack_split(tb[i].z, tb[i].w, h, l);
                Bhi[cur][am[i]][kq + 1] = h; Blo[cur][am[i]][kq + 1] = l;
            } else {
                pack_split(nb0[i].x, nb1[i].x, h, l);     // j = 2*jq
                Bhi[cur][2 * jq[i]][kp[i]] = h;     Blo[cur][2 * jq[i]][kp[i]] = l;
                pack_split(nb0[i].y, nb1[i].y, h, l);     // j = 2*jq+1
                Bhi[cur][2 * jq[i] + 1][kp[i]] = h; Blo[cur][2 * jq[i] + 1][kp[i]] = l;
            }
        }
        __syncthreads();

        // ---- prefetch next chunk ----
        if (kc + 1 < NCHUNK) {
            const int ko = (kc + 1) * 32;
            #pragma unroll
            for (int i = 0; i < 4; i++) {
                ar[i] = *(const float4*)(ap[i] + ko);
                if (BK_CONTIG) {
                    tb[i] = *(const float4*)(tp[i] + ko);
                } else {
                    const size_t ro = (size_t)ko * H_DIM;
                    nb0[i] = *(const float2*)(np[i] + ro);
                    nb1[i] = *(const float2*)(np[i] + ro + H_DIM);
                }
            }
        }

        // ---- two k16 halves: fragments + mma, no split ops ----
        #pragma unroll
        for (int half = 0; half < 2; half++) {
            const int o2 = half * 8;                   // k-pair offset
            uint32_t ah[4], al[4];
            ah[0] = Ahi[cur][mrow    ][o2 + t];     al[0] = Alo[cur][mrow    ][o2 + t];
            ah[1] = Ahi[cur][mrow + 8][o2 + t];     al[1] = Alo[cur][mrow + 8][o2 + t];
            ah[2] = Ahi[cur][mrow    ][o2 + t + 4]; al[2] = Alo[cur][mrow    ][o2 + t + 4];
            ah[3] = Ahi[cur][mrow + 8][o2 + t + 4]; al[3] = Alo[cur][mrow + 8][o2 + t + 4];
            #pragma unroll
            for (int nt = 0; nt < 8; nt++) {
                const int bn = nt * 8 + g;
                uint32_t bh0 = Bhi[cur][bn][o2 + t], bh1 = Bhi[cur][bn][o2 + t + 4];
                uint32_t bl0 = Blo[cur][bn][o2 + t], bl1 = Blo[cur][bn][o2 + t + 4];
                mma_bf16(acc[nt], ah, bh0, bh1);   // hi*hi
                mma_bf16(acc[nt], ah, bl0, bl1);   // hi*lo
                mma_bf16(acc[nt], al, bh0, bh1);   // lo*hi
            }
        }
        // single barrier per chunk: stores for chunk kc+2 (same buffer) happen
        // only after barrier kc+1, which all warps reach after reading chunk kc.
    }

    // epilogue: c0=(g,2t) c1=(g,2t+1) c2=(g+8,2t) c3=(g+8,2t+1) per n-tile
    #pragma unroll
    for (int nt = 0; nt < 8; nt++) {
        const int col = j0 + nt * 8 + 2 * t;
        *(float2*)&g_part[kz][mrow    ][col] = make_float2(acc[nt][0], acc[nt][1]);
        *(float2*)&g_part[kz][mrow + 8][col] = make_float2(acc[nt][2], acc[nt][3]);
    }
}

// ============================================================================
// z-split reduce (16 planes): lane = (zq<<3)|jj; each lane sums 4 planes, then
// 2 shfl rounds (fixed order, deterministic).
// ============================================================================
static __device__ __forceinline__ float4 zsplit_sum(int cap, int j, int zq) {
    float4 a = make_float4(0.f, 0.f, 0.f, 0.f);
    #pragma unroll
    for (int i = 0; i < 4; i++) {
        float4 p = *(const float4*)&g_part[zq * 4 + i][cap][j];
        a.x += p.x; a.y += p.y; a.z += p.z; a.w += p.w;
    }
    #pragma unroll
    for (int o = 8; o <= 16; o <<= 1) {
        a.x += __shfl_xor_sync(0xffffffffu, a.x, o);
        a.y += __shfl_xor_sync(0xffffffffu, a.y, o);
        a.z += __shfl_xor_sync(0xffffffffu, a.z, o);
        a.w += __shfl_xor_sync(0xffffffffu, a.w, o);
    }
    return a;
}

// ============================================================================
// reduce_c_norm: out[cap][:] = sum_z g_part[z][cap][:] (RAW c); g_nrm2 partials.
//   grid (16, 64) = 1024 CTAs, block 128.
// ============================================================================
__global__ void __launch_bounds__(128) reduce_c_norm_kernel(float* __restrict__ out) {
    const int cap = blockIdx.y;
    const int jb = blockIdx.x;
    const int tid = threadIdx.x;
    const int w = tid >> 5, lane = tid & 31;
    const int jj = lane & 7, zq = lane >> 3;
    const int j = (jb * 32 + w * 8 + jj) * 4;

    float4 a = zsplit_sum(cap, j, zq);
    if (zq == 0) *(float4*)(out + cap * H_DIM + j) = a;

    float sq = a.x * a.x + a.y * a.y + a.z * a.z + a.w * a.w;
    #pragma unroll
    for (int o = 1; o <= 4; o <<= 1) sq += __shfl_xor_sync(0xffffffffu, sq, o);
    __shared__ float ws[4];
    if (lane == 0) ws[w] = sq;
    __syncthreads();
    if (tid == 0) g_nrm2[cap][jb] = (ws[0] + ws[1]) + (ws[2] + ws[3]);
}

// ============================================================================
// squash_scale (final iteration only): coeff from 16 norm partials; scale out.
// ============================================================================
__global__ void __launch_bounds__(256) squash_scale_kernel(float* __restrict__ out) {
    const int cap = blockIdx.x;
    const int tid = threadIdx.x;
    __shared__ float coeff_s;
    if (tid == 0) {
        float s = 0.f;
        #pragma unroll
        for (int k = 0; k < 16; k++) s += g_nrm2[cap][k];
        coeff_s = s / (1.0f + s) / sqrtf(s + 1e-9f);
    }
    __syncthreads();
    const float co = coeff_s;
    float* row = out + cap * H_DIM;
    #pragma unroll
    for (int r = 0; r < 2; r++) {
        int j = (tid + 256 * r) * 4;
        float4 v = *(float4*)(row + j);
        *(float4*)(row + j) = make_float4(v.x * co, v.y * co, v.z * co, v.w * co);
    }
}

// ============================================================================
// b_update<FIRST> (fused): coeff from g_nrm2; v = co * sum_z part[z][cap][:]
// -> smem; b[cap,s] (=|+=) x[cap,s,:] . v.  grid (4, 64), block 1024; warp/s.
// ============================================================================
template <bool FIRST>
__global__ void __launch_bounds__(1024) b_update_kernel(const float* __restrict__ x) {
    const int cap = blockIdx.y;
    const int sb = blockIdx.x;
    const int tid = threadIdx.x;
    __shared__ float vs[H_DIM];
    __shared__ float coeff_s;

    if (tid == 0) {
        float s = 0.f;
        #pragma unroll
        for (int k = 0; k < 16; k++) s += g_nrm2[cap][k];
        coeff_s = s / (1.0f + s) / sqrtf(s + 1e-9f);
    }
    __syncthreads();
    const float co = coeff_s;

    if (tid < 512) {
        const int j = tid * 4;
        float4 a = make_float4(0.f, 0.f, 0.f, 0.f);
        #pragma unroll
        for (int z = 0; z < KSPLIT; z++) {
            float4 p = *(const float4*)&g_part[z][cap][j];
            a.x += p.x; a.y += p.y; a.z += p.z; a.w += p.w;
        }
        *(float4*)(vs + j) = make_float4(a.x * co, a.y * co, a.z * co, a.w * co);
    }
    __syncthreads();

    const int warp = tid >> 5, lane = tid & 31;
    const int s = sb * 32 + warp;
    const float4* xp = (const float4*)(x + ((size_t)cap * S_LEN + s) * H_DIM);
    const float4* vp = (const float4*)vs;
    float acc = 0.f;
    #pragma unroll 4
    for (int j = lane; j < H_DIM / 4; j += 32) {
        float4 ev = xp[j], cv = vp[j];
        acc = fmaf(ev.x, cv.x, acc);
        acc = fmaf(ev.y, cv.y, acc);
        acc = fmaf(ev.z, cv.z, acc);
        acc = fmaf(ev.w, cv.w, acc);
    }
    #pragma unroll
    for (int o = 16; o > 0; o >>= 1) acc += __shfl_xor_sync(0xffffffffu, acc, o);
    if (lane == 0) {
        if (FIRST) g_b[cap * S_LEN + s] = acc;
        else       g_b[cap * S_LEN + s] += acc;
    }
}

// ============================================================================
// kernel_launch
// ============================================================================
extern "C" void kernel_launch(void* const* d_in, const int* in_sizes, int n_in,
                              void* d_out, int out_size) {
    const float* x = (const float*)d_in[0];   // [64,128,2048] fp32
    const float* W = (const float*)d_in[1];   // [2048,2048] fp32
    float* out = (float*)d_out;               // [64,2048] fp32 — holds c

    float* u_ptr;
    cudaGetSymbolAddress((void**)&u_ptr, g_u);

    const dim3 gemm_grid(H_DIM / 64, KSPLIT);
    const dim3 ugrid(H_DIM / 256, C_CAPS);
    const dim3 rgrid(16, C_CAPS);
    const dim3 bgrid(4, C_CAPS);

    // iteration 0 (b == 0: uniform softmax; b stored, not accumulated)
    u_kernel<true><<<ugrid, 256>>>(x);
    gemm_mma_kernel<false><<<gemm_grid, 128>>>(u_ptr, W);
    reduce_c_norm_kernel<<<rgrid, 128>>>(out);
    gemm_mma_kernel<true><<<gemm_grid, 128>>>(out, W);
    b_update_kernel<true><<<bgrid, 1024>>>(x);

    // iteration 1
    u_kernel<false><<<ugrid, 256>>>(x);
    gemm_mma_kernel<false><<<gemm_grid, 128>>>(u_ptr, W);
    reduce_c_norm_kernel<<<rgrid, 128>>>(out);
    gemm_mma_kernel<true><<<gemm_grid, 128>>>(out, W);
    b_update_kernel<false><<<bgrid, 1024>>>(x);

    // iteration 2 (final: squash the output)
    u_kernel<false><<<ugrid, 256>>>(x);
    gemm_mma_kernel<false><<<gemm_grid, 128>>>(u_ptr, W);
    reduce_c_norm_kernel<<<rgrid, 128>>>(out);
    squash_scale_kernel<<<C_CAPS, 256>>>(out);
}